// round 9
// baseline (speedup 1.0000x reference)
#include <cuda_runtime.h>

#define BB    16
#define NN    512
#define DDIM  16
#define KNN   20
#define CC    30
#define FF    50
#define NCLS  40
#define NT    256      // threads per block (8 warps)
#define WPB   8
#define BPB   64       // blocks per batch (grid.x); 1 query per warp
#define STRIDE 20      // floats per tile row: 16 coords + sq at [16] (conflict-free)
#define FULLM 0xFFFFFFFFu

// Scratch (device globals — no allocation allowed)
__device__ float g_feat[BB * NN * DDIM];
__device__ float g_pooled[BB * NN];

extern __shared__ char smem_raw[];

__device__ __forceinline__ unsigned forder(float f) {
    unsigned u = __float_as_uint(f);
    return u ^ (((unsigned)((int)u >> 31)) | 0x80000000u);
}

// in-register bitonic sort of 16 u64 keys, ascending
__device__ __forceinline__ void sort16(unsigned long long* keys) {
    #pragma unroll
    for (int k = 2; k <= 16; k <<= 1) {
        #pragma unroll
        for (int j = k >> 1; j > 0; j >>= 1) {
            #pragma unroll
            for (int i = 0; i < 16; i++) {
                int l = i ^ j;
                if (l > i) {
                    bool up = ((i & k) == 0);
                    unsigned long long a = keys[i], b = keys[l];
                    bool sw = up ? (a > b) : (a < b);
                    keys[i] = sw ? b : a;
                    keys[l] = sw ? a : b;
                }
            }
        }
    }
}

// distances (shifted by -sq[n]: same ordering) of this lane's 16 candidates
// j = lane+32i to query n -> packed (dist,idx) keys
__device__ __forceinline__ void dist16(
    const float* __restrict__ tile, int n, int lane, unsigned long long* keys)
{
    const float4* qr = (const float4*)(tile + n * STRIDE);
    float4 q0 = qr[0], q1 = qr[1], q2 = qr[2], q3 = qr[3];
    #pragma unroll
    for (int i = 0; i < 16; i++) {
        int j = lane + 32 * i;
        const float* rp = tile + j * STRIDE;
        const float4* rr = (const float4*)rp;
        float4 r0 = rr[0], r1 = rr[1], r2 = rr[2], r3 = rr[3];
        float dot = q0.x * r0.x;
        dot = fmaf(q0.y, r0.y, dot); dot = fmaf(q0.z, r0.z, dot); dot = fmaf(q0.w, r0.w, dot);
        dot = fmaf(q1.x, r1.x, dot); dot = fmaf(q1.y, r1.y, dot); dot = fmaf(q1.z, r1.z, dot); dot = fmaf(q1.w, r1.w, dot);
        dot = fmaf(q2.x, r2.x, dot); dot = fmaf(q2.y, r2.y, dot); dot = fmaf(q2.z, r2.z, dot); dot = fmaf(q2.w, r2.w, dot);
        dot = fmaf(q3.x, r3.x, dot); dot = fmaf(q3.y, r3.y, dot); dot = fmaf(q3.z, r3.z, dot); dot = fmaf(q3.w, r3.w, dot);
        float dist = fmaf(-2.f, dot, rp[16]);   // sq[j] - 2*dot  (order-equivalent)
        keys[i] = ((unsigned long long)forder(dist) << 32) | (unsigned)j;
    }
}

// One double-pop tournament round over sorted per-lane lists (exact, unique keys;
// ties -> lowest index == stable jax top_k). Emits the two winner indices j1, j2
// (valid in ALL lanes) and advances the register shift-list.
#define TQ_ROUND(keys, J1, J2)                                                  \
    {                                                                           \
        unsigned hi0 = (unsigned)((keys)[0] >> 32), lo0 = (unsigned)(keys)[0];  \
        unsigned hi1 = (unsigned)((keys)[1] >> 32), lo1 = (unsigned)(keys)[1];  \
        unsigned mhi1 = __reduce_min_sync(FULLM, hi0);                          \
        unsigned c1   = (hi0 == mhi1) ? lo0 : FULLM;                            \
        unsigned mlo1 = __reduce_min_sync(FULLM, c1);                           \
        bool win1 = (hi0 == mhi1) && (lo0 == mlo1);                             \
        unsigned chi = win1 ? hi1 : hi0, clo = win1 ? lo1 : lo0;                \
        unsigned mhi2 = __reduce_min_sync(FULLM, chi);                          \
        unsigned c2   = (chi == mhi2) ? clo : FULLM;                            \
        unsigned mlo2 = __reduce_min_sync(FULLM, c2);                           \
        bool win2 = (chi == mhi2) && (clo == mlo2);                             \
        (J1) = mlo1; (J2) = mlo2;                                               \
        int adv = (int)win1 + (int)win2;                                        \
        if (adv) {                                                              \
            _Pragma("unroll")                                                   \
            for (int _i = 0; _i < 15; _i++) (keys)[_i] = (keys)[_i + 1];        \
            (keys)[15] = ~0ull;                                                 \
            if (adv == 2) {                                                     \
                _Pragma("unroll")                                               \
                for (int _i = 0; _i < 15; _i++) (keys)[_i] = (keys)[_i + 1];    \
                (keys)[15] = ~0ull;                                             \
            }                                                                   \
        }                                                                       \
    }

// shared tile setup: load x[b] transposed into [512][20] with sq in column 16
__device__ __forceinline__ void load_tile(float* tile, const float4* x4, int tid)
{
    #pragma unroll
    for (int i = tid; i < NN * DDIM / 4; i += NT) {
        int row = i >> 2, part = i & 3;
        *(float4*)(tile + row * STRIDE + part * 4) = x4[i];
    }
    __syncthreads();
    #pragma unroll
    for (int r = tid; r < NN; r += NT) {
        const float* rp = tile + r * STRIDE;
        float s = rp[0] * rp[0];
        #pragma unroll
        for (int d = 1; d < DDIM; d++) s = fmaf(rp[d], rp[d], s);
        tile[r * STRIDE + 16] = s;     // same fma order as dist16 -> self strictly min
    }
}

// ---------------------------------------------------------------------------
// Stage 1: KNN on raw points + weighted Frechet mean, fused into the rounds.
// ---------------------------------------------------------------------------
__global__ void __launch_bounds__(NT, 4) stage1_kernel(
    const float* __restrict__ x, const float* __restrict__ w_fm1)
{
    float* tile = (float*)smem_raw;                // [512][20]
    float* wc   = tile + NN * STRIDE;              // [20]

    const int tid = threadIdx.x, lane = tid & 31, warp = tid >> 5;
    const int b = blockIdx.y;

    load_tile(tile, (const float4*)(x + (size_t)b * NN * DDIM), tid);
    if (tid == 0) {
        float mx = -1e30f;
        for (int k = 0; k < KNN; k++) mx = fmaxf(mx, w_fm1[k]);
        float e[KNN], s = 0.f;
        for (int k = 0; k < KNN; k++) { e[k] = expf(w_fm1[k] - mx); s += e[k]; }
        float inv = 1.f / s;
        for (int k = 0; k < KNN; k++) wc[k] = e[k] * inv;
    }
    __syncthreads();

    const int n = blockIdx.x * WPB + warp;         // 1 query per warp
    unsigned long long keys[16];
    dist16(tile, n, lane, keys);
    sort16(keys);

    const int d = lane & 15;
    float acc = 0.f;
    #pragma unroll
    for (int r = 0; r < KNN / 2; r++) {
        unsigned j1, j2;
        TQ_ROUND(keys, j1, j2);
        // fused weighted mean: winners broadcast in all lanes, LDS broadcast reads
        acc = fmaf(wc[2 * r],     tile[j1 * STRIDE + d], acc);
        acc = fmaf(wc[2 * r + 1], tile[j2 * STRIDE + d], acc);
    }
    if (lane < DDIM)
        g_feat[((size_t)b * NN + n) * DDIM + lane] = acc;
}

// ---------------------------------------------------------------------------
// Stage 2: KNN on g (same ordering as KNN on the rank-1 lifted features),
// fm2[d,f] = sum_k g[nn_k,d]*A[k,f] fused into the rounds,
// A = sum_c softmax(w_fm2)[c,:]*w_mix1[c]*w_mix2[c,:],
// pooled[n] = mean_f sqrt(sum_d (fm2[d,f]-m_last[d,f])^2 + 1e-8)
// ---------------------------------------------------------------------------
__global__ void __launch_bounds__(NT, 3) stage2_kernel(
    const float* __restrict__ w_fm2, const float* __restrict__ w_mix1,
    const float* __restrict__ w_mix2, const float* __restrict__ m_last)
{
    float* tile = (float*)smem_raw;                // [512][20]
    float* A    = tile + NN * STRIDE;              // [20][50]
    float* ms   = A + KNN * FF;                    // [16][50]
    float* wc2  = ms + DDIM * FF;                  // [30][20]

    const int tid = threadIdx.x, lane = tid & 31, warp = tid >> 5;
    const int b = blockIdx.y;

    load_tile(tile, (const float4*)(g_feat + (size_t)b * NN * DDIM), tid);
    if (tid < CC) {
        const float* row = w_fm2 + tid * KNN;
        float mx = -1e30f;
        for (int k = 0; k < KNN; k++) mx = fmaxf(mx, row[k]);
        float e[KNN], s = 0.f;
        for (int k = 0; k < KNN; k++) { e[k] = expf(row[k] - mx); s += e[k]; }
        float inv = 1.f / s;
        for (int k = 0; k < KNN; k++) wc2[tid * KNN + k] = e[k] * inv;
    }
    for (int i = tid; i < DDIM * FF; i += NT) ms[i] = m_last[i];
    __syncthreads();
    // A[k][f] = sum_c wc2[c][k] * w_mix1[c] * w_mix2[c][f]
    for (int i = tid; i < KNN * FF; i += NT) {
        int k = i / FF, f = i % FF;
        float acc = 0.f;
        #pragma unroll
        for (int c = 0; c < CC; c++)
            acc = fmaf(wc2[c * KNN + k] * __ldg(w_mix1 + c), __ldg(w_mix2 + c * FF + f), acc);
        A[i] = acc;
    }
    __syncthreads();

    const int n = blockIdx.x * WPB + warp;
    unsigned long long keys[16];
    dist16(tile, n, lane, keys);
    sort16(keys);

    const int f0 = lane, f1 = lane + 32;
    const bool v1 = (f1 < FF);
    float acc0[DDIM], acc1[DDIM];
    #pragma unroll
    for (int dd = 0; dd < DDIM; dd++) { acc0[dd] = 0.f; acc1[dd] = 0.f; }

    #pragma unroll
    for (int r = 0; r < KNN / 2; r++) {
        unsigned j1, j2;
        TQ_ROUND(keys, j1, j2);
        // fused fm2 accumulation for ranks 2r and 2r+1 (fills REDUX bubbles)
        #pragma unroll
        for (int s = 0; s < 2; s++) {
            const int k = 2 * r + s;
            const unsigned jj = s ? j2 : j1;
            float a0 = A[k * FF + f0];
            float a1 = v1 ? A[k * FF + f1] : 0.f;
            const float4* row = (const float4*)(tile + jj * STRIDE);
            float4 r0 = row[0], r1 = row[1], r2 = row[2], r3 = row[3];
            acc0[ 0] = fmaf(r0.x, a0, acc0[ 0]); acc1[ 0] = fmaf(r0.x, a1, acc1[ 0]);
            acc0[ 1] = fmaf(r0.y, a0, acc0[ 1]); acc1[ 1] = fmaf(r0.y, a1, acc1[ 1]);
            acc0[ 2] = fmaf(r0.z, a0, acc0[ 2]); acc1[ 2] = fmaf(r0.z, a1, acc1[ 2]);
            acc0[ 3] = fmaf(r0.w, a0, acc0[ 3]); acc1[ 3] = fmaf(r0.w, a1, acc1[ 3]);
            acc0[ 4] = fmaf(r1.x, a0, acc0[ 4]); acc1[ 4] = fmaf(r1.x, a1, acc1[ 4]);
            acc0[ 5] = fmaf(r1.y, a0, acc0[ 5]); acc1[ 5] = fmaf(r1.y, a1, acc1[ 5]);
            acc0[ 6] = fmaf(r1.z, a0, acc0[ 6]); acc1[ 6] = fmaf(r1.z, a1, acc1[ 6]);
            acc0[ 7] = fmaf(r1.w, a0, acc0[ 7]); acc1[ 7] = fmaf(r1.w, a1, acc1[ 7]);
            acc0[ 8] = fmaf(r2.x, a0, acc0[ 8]); acc1[ 8] = fmaf(r2.x, a1, acc1[ 8]);
            acc0[ 9] = fmaf(r2.y, a0, acc0[ 9]); acc1[ 9] = fmaf(r2.y, a1, acc1[ 9]);
            acc0[10] = fmaf(r2.z, a0, acc0[10]); acc1[10] = fmaf(r2.z, a1, acc1[10]);
            acc0[11] = fmaf(r2.w, a0, acc0[11]); acc1[11] = fmaf(r2.w, a1, acc1[11]);
            acc0[12] = fmaf(r3.x, a0, acc0[12]); acc1[12] = fmaf(r3.x, a1, acc1[12]);
            acc0[13] = fmaf(r3.y, a0, acc0[13]); acc1[13] = fmaf(r3.y, a1, acc1[13]);
            acc0[14] = fmaf(r3.z, a0, acc0[14]); acc1[14] = fmaf(r3.z, a1, acc1[14]);
            acc0[15] = fmaf(r3.w, a0, acc0[15]); acc1[15] = fmaf(r3.w, a1, acc1[15]);
        }
    }

    float s0 = 0.f, s1 = 0.f;
    #pragma unroll
    for (int dd = 0; dd < DDIM; dd++) {
        float d0 = acc0[dd] - ms[dd * FF + f0];
        s0 = fmaf(d0, d0, s0);
        float d1 = acc1[dd] - (v1 ? ms[dd * FF + f1] : 0.f);
        s1 = fmaf(d1, d1, s1);
    }
    float per = sqrtf(s0 + 1e-8f) + (v1 ? sqrtf(s1 + 1e-8f) : 0.f);
    #pragma unroll
    for (int off = 16; off; off >>= 1)
        per += __shfl_xor_sync(FULLM, per, off);
    if (lane == 0)
        g_pooled[(size_t)b * NN + n] = per * (1.f / (float)FF);
}

// ---------------------------------------------------------------------------
// Final classifier: out[b][j] = sum_n pooled[b][n]*w_cls[n][j] + b_cls[j]
// ---------------------------------------------------------------------------
__global__ void __launch_bounds__(512) cls_kernel(
    const float* __restrict__ w_cls, const float* __restrict__ b_cls,
    float* __restrict__ out)
{
    __shared__ float ps[NN];
    const int tid = threadIdx.x;
    const int b = blockIdx.x;
    ps[tid] = g_pooled[(size_t)b * NN + tid];
    __syncthreads();
    if (tid < NCLS) {
        float a0 = 0.f, a1 = 0.f, a2 = 0.f, a3 = 0.f;
        #pragma unroll 4
        for (int n = 0; n < NN; n += 4) {
            a0 = fmaf(ps[n + 0], w_cls[(n + 0) * NCLS + tid], a0);
            a1 = fmaf(ps[n + 1], w_cls[(n + 1) * NCLS + tid], a1);
            a2 = fmaf(ps[n + 2], w_cls[(n + 2) * NCLS + tid], a2);
            a3 = fmaf(ps[n + 3], w_cls[(n + 3) * NCLS + tid], a3);
        }
        out[b * NCLS + tid] = (a0 + a1) + (a2 + a3) + b_cls[tid];
    }
}

extern "C" void kernel_launch(void* const* d_in, const int* in_sizes, int n_in,
                              void* d_out, int out_size)
{
    const float* x      = (const float*)d_in[0];  // [16,512,16,1]
    const float* w_fm1  = (const float*)d_in[1];  // [1,20]
    const float* w_mix1 = (const float*)d_in[2];  // [1,30]
    const float* w_fm2  = (const float*)d_in[3];  // [30,20]
    const float* w_mix2 = (const float*)d_in[4];  // [30,50]
    const float* m_last = (const float*)d_in[5];  // [16,50]
    const float* w_cls  = (const float*)d_in[6];  // [512,40]
    const float* b_cls  = (const float*)d_in[7];  // [40]
    float* out = (float*)d_out;                   // [16,40]

    constexpr size_t S1_SMEM = ((size_t)NN * STRIDE + KNN) * 4;                     // 41040
    constexpr size_t S2_SMEM = ((size_t)NN * STRIDE + KNN * FF + DDIM * FF
                               + CC * KNN) * 4;                                     // 50560

    cudaFuncSetAttribute(stage1_kernel, cudaFuncAttributeMaxDynamicSharedMemorySize, (int)S1_SMEM);
    cudaFuncSetAttribute(stage2_kernel, cudaFuncAttributeMaxDynamicSharedMemorySize, (int)S2_SMEM);

    dim3 grid(BPB, BB);   // 64 x 16 = 1024 blocks, 1 query per warp
    stage1_kernel<<<grid, NT, S1_SMEM>>>(x, w_fm1);
    stage2_kernel<<<grid, NT, S2_SMEM>>>(w_fm2, w_mix1, w_mix2, m_last);
    cls_kernel<<<BB, 512>>>(w_cls, b_cls, out);
}

// round 10
// speedup vs baseline: 1.1588x; 1.1588x over previous
#include <cuda_runtime.h>

#define BB    16
#define NN    512
#define DDIM  16
#define KNN   20
#define CC    30
#define FF    50
#define NCLS  40
#define NT    256      // threads per block (8 warps)
#define WPB   8
#define BPB   64       // blocks per batch (grid.x); 1 query per warp
#define STRIDE 20      // floats per tile row: 16 coords + sq at [16] (conflict-free)
#define FULLM 0xFFFFFFFFu

// Scratch (device globals — no allocation allowed)
__device__ float g_feat[BB * NN * DDIM];
__device__ float g_pooled[BB * NN];

extern __shared__ char smem_raw[];

__device__ __forceinline__ unsigned forder(float f) {
    unsigned u = __float_as_uint(f);
    return u ^ (((unsigned)((int)u >> 31)) | 0x80000000u);
}

// in-register bitonic sort of 16 u64 keys, ascending
__device__ __forceinline__ void sort16(unsigned long long* keys) {
    #pragma unroll
    for (int k = 2; k <= 16; k <<= 1) {
        #pragma unroll
        for (int j = k >> 1; j > 0; j >>= 1) {
            #pragma unroll
            for (int i = 0; i < 16; i++) {
                int l = i ^ j;
                if (l > i) {
                    bool up = ((i & k) == 0);
                    unsigned long long a = keys[i], b = keys[l];
                    bool sw = up ? (a > b) : (a < b);
                    keys[i] = sw ? b : a;
                    keys[l] = sw ? a : b;
                }
            }
        }
    }
}

// distances (shifted by -sq[n]: same ordering) of this lane's 16 candidates
// j = lane+32i to query n -> packed (dist,idx) keys
__device__ __forceinline__ void dist16(
    const float* __restrict__ tile, int n, int lane, unsigned long long* keys)
{
    const float4* qr = (const float4*)(tile + n * STRIDE);
    float4 q0 = qr[0], q1 = qr[1], q2 = qr[2], q3 = qr[3];
    #pragma unroll
    for (int i = 0; i < 16; i++) {
        int j = lane + 32 * i;
        const float* rp = tile + j * STRIDE;
        const float4* rr = (const float4*)rp;
        float4 r0 = rr[0], r1 = rr[1], r2 = rr[2], r3 = rr[3];
        float dot = q0.x * r0.x;
        dot = fmaf(q0.y, r0.y, dot); dot = fmaf(q0.z, r0.z, dot); dot = fmaf(q0.w, r0.w, dot);
        dot = fmaf(q1.x, r1.x, dot); dot = fmaf(q1.y, r1.y, dot); dot = fmaf(q1.z, r1.z, dot); dot = fmaf(q1.w, r1.w, dot);
        dot = fmaf(q2.x, r2.x, dot); dot = fmaf(q2.y, r2.y, dot); dot = fmaf(q2.z, r2.z, dot); dot = fmaf(q2.w, r2.w, dot);
        dot = fmaf(q3.x, r3.x, dot); dot = fmaf(q3.y, r3.y, dot); dot = fmaf(q3.z, r3.z, dot); dot = fmaf(q3.w, r3.w, dot);
        float dist = fmaf(-2.f, dot, rp[16]);   // sq[j] - 2*dot  (order-equivalent)
        keys[i] = ((unsigned long long)forder(dist) << 32) | (unsigned)j;
    }
}

// One double-pop tournament round (exact, unique keys; ties -> lowest index ==
// stable jax top_k). Emits winner indices J1, J2 (valid in ALL lanes).
// BRANCHLESS list advance: each lane shifts by its own win count via selects.
#define TQ_ROUND(keys, J1, J2)                                                  \
    {                                                                           \
        unsigned hi0 = (unsigned)((keys)[0] >> 32), lo0 = (unsigned)(keys)[0];  \
        unsigned hi1 = (unsigned)((keys)[1] >> 32), lo1 = (unsigned)(keys)[1];  \
        unsigned mhi1 = __reduce_min_sync(FULLM, hi0);                          \
        unsigned c1   = (hi0 == mhi1) ? lo0 : FULLM;                            \
        unsigned mlo1 = __reduce_min_sync(FULLM, c1);                           \
        bool win1 = (hi0 == mhi1) && (lo0 == mlo1);                             \
        unsigned chi = win1 ? hi1 : hi0, clo = win1 ? lo1 : lo0;                \
        unsigned mhi2 = __reduce_min_sync(FULLM, chi);                          \
        unsigned c2   = (chi == mhi2) ? clo : FULLM;                            \
        unsigned mlo2 = __reduce_min_sync(FULLM, c2);                           \
        bool win2 = (chi == mhi2) && (clo == mlo2);                             \
        (J1) = mlo1; (J2) = mlo2;                                               \
        int adv = (int)win1 + (int)win2;                                        \
        _Pragma("unroll")                                                       \
        for (int _i = 0; _i < 16; _i++) {                                       \
            unsigned long long _k1 = (_i + 1 < 16) ? (keys)[_i + 1] : ~0ull;    \
            unsigned long long _k2 = (_i + 2 < 16) ? (keys)[_i + 2] : ~0ull;    \
            (keys)[_i] = (adv == 0) ? (keys)[_i] : ((adv == 1) ? _k1 : _k2);    \
        }                                                                       \
    }

// Exact ranked top-20 (unfused form): lane r (r<20) ends holding the index of
// the r-th nearest neighbor. keys are fully consumed (dead afterwards).
__device__ __forceinline__ unsigned topk20(unsigned long long* keys, int lane)
{
    unsigned sel = 0;
    #pragma unroll
    for (int r = 0; r < KNN / 2; r++) {
        unsigned j1, j2;
        TQ_ROUND(keys, j1, j2);
        if (lane == 2 * r)     sel = j1;
        if (lane == 2 * r + 1) sel = j2;
    }
    return sel;
}

// shared tile setup: load x[b] transposed into [512][20] with sq in column 16
__device__ __forceinline__ void load_tile(float* tile, const float4* x4, int tid)
{
    #pragma unroll
    for (int i = tid; i < NN * DDIM / 4; i += NT) {
        int row = i >> 2, part = i & 3;
        *(float4*)(tile + row * STRIDE + part * 4) = x4[i];
    }
    __syncthreads();
    #pragma unroll
    for (int r = tid; r < NN; r += NT) {
        const float* rp = tile + r * STRIDE;
        float s = rp[0] * rp[0];
        #pragma unroll
        for (int d = 1; d < DDIM; d++) s = fmaf(rp[d], rp[d], s);
        tile[r * STRIDE + 16] = s;     // same fma order as dist16 -> self strictly min
    }
}

// ---------------------------------------------------------------------------
// Stage 1: KNN on raw points + weighted Frechet mean fused into the rounds.
// ---------------------------------------------------------------------------
__global__ void __launch_bounds__(NT, 4) stage1_kernel(
    const float* __restrict__ x, const float* __restrict__ w_fm1)
{
    float* tile = (float*)smem_raw;                // [512][20]
    float* wc   = tile + NN * STRIDE;              // [20]

    const int tid = threadIdx.x, lane = tid & 31, warp = tid >> 5;
    const int b = blockIdx.y;

    load_tile(tile, (const float4*)(x + (size_t)b * NN * DDIM), tid);
    if (tid == 0) {
        float mx = -1e30f;
        for (int k = 0; k < KNN; k++) mx = fmaxf(mx, w_fm1[k]);
        float e[KNN], s = 0.f;
        for (int k = 0; k < KNN; k++) { e[k] = expf(w_fm1[k] - mx); s += e[k]; }
        float inv = 1.f / s;
        for (int k = 0; k < KNN; k++) wc[k] = e[k] * inv;
    }
    __syncthreads();

    const int n = blockIdx.x * WPB + warp;         // 1 query per warp
    unsigned long long keys[16];
    dist16(tile, n, lane, keys);
    sort16(keys);

    const int d = lane & 15;
    float acc = 0.f;
    #pragma unroll
    for (int r = 0; r < KNN / 2; r++) {
        unsigned j1, j2;
        TQ_ROUND(keys, j1, j2);
        // fused weighted mean: winners broadcast in all lanes, LDS broadcast reads
        acc = fmaf(wc[2 * r],     tile[j1 * STRIDE + d], acc);
        acc = fmaf(wc[2 * r + 1], tile[j2 * STRIDE + d], acc);
    }
    if (lane < DDIM)
        g_feat[((size_t)b * NN + n) * DDIM + lane] = acc;
}

// ---------------------------------------------------------------------------
// Stage 2: KNN on g (same ordering as KNN on the rank-1 lifted features),
// UNFUSED epilogue (keys die before the 64 accumulators go live -> fits occ 4):
// fm2[d,f] = sum_k g[nn_k,d]*A[k,f],  A = sum_c softmax(w_fm2)[c,:]*w_mix1[c]*w_mix2[c,:]
// pooled[n] = mean_f sqrt(sum_d (fm2[d,f]-m_last[d,f])^2 + 1e-8)
// ---------------------------------------------------------------------------
__global__ void __launch_bounds__(NT, 4) stage2_kernel(
    const float* __restrict__ w_fm2, const float* __restrict__ w_mix1,
    const float* __restrict__ w_mix2, const float* __restrict__ m_last)
{
    float* tile = (float*)smem_raw;                // [512][20]
    float* A    = tile + NN * STRIDE;              // [20][50]
    float* ms   = A + KNN * FF;                    // [16][50]
    float* wc2  = ms + DDIM * FF;                  // [30][20]

    const int tid = threadIdx.x, lane = tid & 31, warp = tid >> 5;
    const int b = blockIdx.y;

    load_tile(tile, (const float4*)(g_feat + (size_t)b * NN * DDIM), tid);
    if (tid < CC) {
        const float* row = w_fm2 + tid * KNN;
        float mx = -1e30f;
        for (int k = 0; k < KNN; k++) mx = fmaxf(mx, row[k]);
        float e[KNN], s = 0.f;
        for (int k = 0; k < KNN; k++) { e[k] = expf(row[k] - mx); s += e[k]; }
        float inv = 1.f / s;
        for (int k = 0; k < KNN; k++) wc2[tid * KNN + k] = e[k] * inv;
    }
    for (int i = tid; i < DDIM * FF; i += NT) ms[i] = m_last[i];
    __syncthreads();
    // A[k][f] = sum_c wc2[c][k] * w_mix1[c] * w_mix2[c][f]
    for (int i = tid; i < KNN * FF; i += NT) {
        int k = i / FF, f = i % FF;
        float acc = 0.f;
        #pragma unroll
        for (int c = 0; c < CC; c++)
            acc = fmaf(wc2[c * KNN + k] * __ldg(w_mix1 + c), __ldg(w_mix2 + c * FF + f), acc);
        A[i] = acc;
    }
    __syncthreads();

    const int n = blockIdx.x * WPB + warp;
    unsigned long long keys[16];
    dist16(tile, n, lane, keys);
    sort16(keys);
    unsigned sel = topk20(keys, lane);             // keys dead after this

    const int f0 = lane, f1 = lane + 32;
    const bool v1 = (f1 < FF);
    float acc0[DDIM], acc1[DDIM];
    #pragma unroll
    for (int dd = 0; dd < DDIM; dd++) { acc0[dd] = 0.f; acc1[dd] = 0.f; }
    #pragma unroll
    for (int k = 0; k < KNN; k++) {
        unsigned idx = __shfl_sync(FULLM, sel, k);
        float a0 = A[k * FF + f0];
        float a1 = v1 ? A[k * FF + f1] : 0.f;
        const float4* row = (const float4*)(tile + idx * STRIDE);
        float4 r0 = row[0], r1 = row[1], r2 = row[2], r3 = row[3];
        acc0[ 0] = fmaf(r0.x, a0, acc0[ 0]); acc1[ 0] = fmaf(r0.x, a1, acc1[ 0]);
        acc0[ 1] = fmaf(r0.y, a0, acc0[ 1]); acc1[ 1] = fmaf(r0.y, a1, acc1[ 1]);
        acc0[ 2] = fmaf(r0.z, a0, acc0[ 2]); acc1[ 2] = fmaf(r0.z, a1, acc1[ 2]);
        acc0[ 3] = fmaf(r0.w, a0, acc0[ 3]); acc1[ 3] = fmaf(r0.w, a1, acc1[ 3]);
        acc0[ 4] = fmaf(r1.x, a0, acc0[ 4]); acc1[ 4] = fmaf(r1.x, a1, acc1[ 4]);
        acc0[ 5] = fmaf(r1.y, a0, acc0[ 5]); acc1[ 5] = fmaf(r1.y, a1, acc1[ 5]);
        acc0[ 6] = fmaf(r1.z, a0, acc0[ 6]); acc1[ 6] = fmaf(r1.z, a1, acc1[ 6]);
        acc0[ 7] = fmaf(r1.w, a0, acc0[ 7]); acc1[ 7] = fmaf(r1.w, a1, acc1[ 7]);
        acc0[ 8] = fmaf(r2.x, a0, acc0[ 8]); acc1[ 8] = fmaf(r2.x, a1, acc1[ 8]);
        acc0[ 9] = fmaf(r2.y, a0, acc0[ 9]); acc1[ 9] = fmaf(r2.y, a1, acc1[ 9]);
        acc0[10] = fmaf(r2.z, a0, acc0[10]); acc1[10] = fmaf(r2.z, a1, acc1[10]);
        acc0[11] = fmaf(r2.w, a0, acc0[11]); acc1[11] = fmaf(r2.w, a1, acc1[11]);
        acc0[12] = fmaf(r3.x, a0, acc0[12]); acc1[12] = fmaf(r3.x, a1, acc1[12]);
        acc0[13] = fmaf(r3.y, a0, acc0[13]); acc1[13] = fmaf(r3.y, a1, acc1[13]);
        acc0[14] = fmaf(r3.z, a0, acc0[14]); acc1[14] = fmaf(r3.z, a1, acc1[14]);
        acc0[15] = fmaf(r3.w, a0, acc0[15]); acc1[15] = fmaf(r3.w, a1, acc1[15]);
    }
    float s0 = 0.f, s1 = 0.f;
    #pragma unroll
    for (int dd = 0; dd < DDIM; dd++) {
        float d0 = acc0[dd] - ms[dd * FF + f0];
        s0 = fmaf(d0, d0, s0);
        float d1 = acc1[dd] - (v1 ? ms[dd * FF + f1] : 0.f);
        s1 = fmaf(d1, d1, s1);
    }
    float per = sqrtf(s0 + 1e-8f) + (v1 ? sqrtf(s1 + 1e-8f) : 0.f);
    #pragma unroll
    for (int off = 16; off; off >>= 1)
        per += __shfl_xor_sync(FULLM, per, off);
    if (lane == 0)
        g_pooled[(size_t)b * NN + n] = per * (1.f / (float)FF);
}

// ---------------------------------------------------------------------------
// Final classifier: out[b][j] = sum_n pooled[b][n]*w_cls[n][j] + b_cls[j]
// Parallelized: 40 classes x 12 n-chunks, smem tree reduce.
// ---------------------------------------------------------------------------
#define CLS_CH 12
__global__ void __launch_bounds__(512) cls_kernel(
    const float* __restrict__ w_cls, const float* __restrict__ b_cls,
    float* __restrict__ out)
{
    __shared__ float ps[NN];
    __shared__ float part[CLS_CH][NCLS];
    const int tid = threadIdx.x;
    const int b = blockIdx.x;
    ps[tid] = g_pooled[(size_t)b * NN + tid];
    __syncthreads();
    if (tid < NCLS * CLS_CH) {
        int j = tid % NCLS, c = tid / NCLS;
        int n0 = c * 43, n1 = min(NN, n0 + 43);
        float a = 0.f;
        for (int n = n0; n < n1; n++)
            a = fmaf(ps[n], w_cls[n * NCLS + j], a);
        part[c][j] = a;
    }
    __syncthreads();
    if (tid < NCLS) {
        float a = b_cls[tid];
        #pragma unroll
        for (int c = 0; c < CLS_CH; c++) a += part[c][tid];
        out[b * NCLS + tid] = a;
    }
}

extern "C" void kernel_launch(void* const* d_in, const int* in_sizes, int n_in,
                              void* d_out, int out_size)
{
    const float* x      = (const float*)d_in[0];  // [16,512,16,1]
    const float* w_fm1  = (const float*)d_in[1];  // [1,20]
    const float* w_mix1 = (const float*)d_in[2];  // [1,30]
    const float* w_fm2  = (const float*)d_in[3];  // [30,20]
    const float* w_mix2 = (const float*)d_in[4];  // [30,50]
    const float* m_last = (const float*)d_in[5];  // [16,50]
    const float* w_cls  = (const float*)d_in[6];  // [512,40]
    const float* b_cls  = (const float*)d_in[7];  // [40]
    float* out = (float*)d_out;                   // [16,40]

    constexpr size_t S1_SMEM = ((size_t)NN * STRIDE + KNN) * 4;                     // 41040
    constexpr size_t S2_SMEM = ((size_t)NN * STRIDE + KNN * FF + DDIM * FF
                               + CC * KNN) * 4;                                     // 50560

    cudaFuncSetAttribute(stage1_kernel, cudaFuncAttributeMaxDynamicSharedMemorySize, (int)S1_SMEM);
    cudaFuncSetAttribute(stage2_kernel, cudaFuncAttributeMaxDynamicSharedMemorySize, (int)S2_SMEM);

    dim3 grid(BPB, BB);   // 64 x 16 = 1024 blocks, 1 query per warp
    stage1_kernel<<<grid, NT, S1_SMEM>>>(x, w_fm1);
    stage2_kernel<<<grid, NT, S2_SMEM>>>(w_fm2, w_mix1, w_mix2, m_last);
    cls_kernel<<<BB, 512>>>(w_cls, b_cls, out);
}

// round 11
// speedup vs baseline: 1.2302x; 1.0616x over previous
#include <cuda_runtime.h>

#define BB    16
#define NN    512
#define DDIM  16
#define KNN   20
#define CC    30
#define FF    50
#define NCLS  40
#define NT    256      // threads per block (8 warps)
#define WPB   8
#define BPB   64       // blocks per batch (grid.x); 1 query per warp
#define STRIDE 20      // floats per tile row: 16 coords + sq at [16] (conflict-free)
#define FULLM 0xFFFFFFFFu

typedef unsigned long long ull;

// Scratch (device globals — no allocation allowed)
__device__ float g_feat[BB * NN * DDIM];
__device__ float g_pooled[BB * NN];

extern __shared__ char smem_raw[];

__device__ __forceinline__ unsigned forder(float f) {
    unsigned u = __float_as_uint(f);
    return u ^ (((unsigned)((int)u >> 31)) | 0x80000000u);
}

__device__ __forceinline__ ull dup2(float v) {
    unsigned u = __float_as_uint(v);
    return ((ull)u << 32) | u;
}

// packed fp32x2 fma: acc = xv2*a2 + acc (two independent IEEE fp32 FMAs)
#define FMA2(acc, xv2, a2) \
    asm("fma.rn.f32x2 %0, %1, %2, %3;" : "=l"(acc) : "l"(xv2), "l"(a2), "l"(acc))

// in-register bitonic sort of 16 u64 keys, ascending
__device__ __forceinline__ void sort16(ull* keys) {
    #pragma unroll
    for (int k = 2; k <= 16; k <<= 1) {
        #pragma unroll
        for (int j = k >> 1; j > 0; j >>= 1) {
            #pragma unroll
            for (int i = 0; i < 16; i++) {
                int l = i ^ j;
                if (l > i) {
                    bool up = ((i & k) == 0);
                    ull a = keys[i], b = keys[l];
                    bool sw = up ? (a > b) : (a < b);
                    keys[i] = sw ? b : a;
                    keys[l] = sw ? a : b;
                }
            }
        }
    }
}

// distances (shifted by -sq[n]: same ordering) of this lane's 16 candidates
// j = lane+32i to query n -> packed (dist,idx) keys
__device__ __forceinline__ void dist16(
    const float* __restrict__ tile, int n, int lane, ull* keys)
{
    const float4* qr = (const float4*)(tile + n * STRIDE);
    float4 q0 = qr[0], q1 = qr[1], q2 = qr[2], q3 = qr[3];
    #pragma unroll
    for (int i = 0; i < 16; i++) {
        int j = lane + 32 * i;
        const float* rp = tile + j * STRIDE;
        const float4* rr = (const float4*)rp;
        float4 r0 = rr[0], r1 = rr[1], r2 = rr[2], r3 = rr[3];
        float dot = q0.x * r0.x;
        dot = fmaf(q0.y, r0.y, dot); dot = fmaf(q0.z, r0.z, dot); dot = fmaf(q0.w, r0.w, dot);
        dot = fmaf(q1.x, r1.x, dot); dot = fmaf(q1.y, r1.y, dot); dot = fmaf(q1.z, r1.z, dot); dot = fmaf(q1.w, r1.w, dot);
        dot = fmaf(q2.x, r2.x, dot); dot = fmaf(q2.y, r2.y, dot); dot = fmaf(q2.z, r2.z, dot); dot = fmaf(q2.w, r2.w, dot);
        dot = fmaf(q3.x, r3.x, dot); dot = fmaf(q3.y, r3.y, dot); dot = fmaf(q3.z, r3.z, dot); dot = fmaf(q3.w, r3.w, dot);
        float dist = fmaf(-2.f, dot, rp[16]);   // sq[j] - 2*dot  (order-equivalent)
        keys[i] = ((ull)forder(dist) << 32) | (unsigned)j;
    }
}

// One double-pop tournament round (exact, unique keys; ties -> lowest index ==
// stable jax top_k). Emits winner indices J1, J2 (valid in ALL lanes).
// BRANCHY advance (measured faster than predicated shift in R10).
#define TQ_ROUND(keys, J1, J2)                                                  \
    {                                                                           \
        unsigned hi0 = (unsigned)((keys)[0] >> 32), lo0 = (unsigned)(keys)[0];  \
        unsigned hi1 = (unsigned)((keys)[1] >> 32), lo1 = (unsigned)(keys)[1];  \
        unsigned mhi1 = __reduce_min_sync(FULLM, hi0);                          \
        unsigned c1   = (hi0 == mhi1) ? lo0 : FULLM;                            \
        unsigned mlo1 = __reduce_min_sync(FULLM, c1);                           \
        bool win1 = (hi0 == mhi1) && (lo0 == mlo1);                             \
        unsigned chi = win1 ? hi1 : hi0, clo = win1 ? lo1 : lo0;                \
        unsigned mhi2 = __reduce_min_sync(FULLM, chi);                          \
        unsigned c2   = (chi == mhi2) ? clo : FULLM;                            \
        unsigned mlo2 = __reduce_min_sync(FULLM, c2);                           \
        bool win2 = (chi == mhi2) && (clo == mlo2);                             \
        (J1) = mlo1; (J2) = mlo2;                                               \
        int adv = (int)win1 + (int)win2;                                        \
        if (adv) {                                                              \
            _Pragma("unroll")                                                   \
            for (int _i = 0; _i < 15; _i++) (keys)[_i] = (keys)[_i + 1];        \
            (keys)[15] = ~0ull;                                                 \
            if (adv == 2) {                                                     \
                _Pragma("unroll")                                               \
                for (int _i = 0; _i < 15; _i++) (keys)[_i] = (keys)[_i + 1];    \
                (keys)[15] = ~0ull;                                             \
            }                                                                   \
        }                                                                       \
    }

// Exact ranked top-20 (unfused): lane r (r<20) ends holding the index of the
// r-th nearest neighbor. keys fully consumed (dead afterwards).
__device__ __forceinline__ unsigned topk20(ull* keys, int lane)
{
    unsigned sel = 0;
    #pragma unroll
    for (int r = 0; r < KNN / 2; r++) {
        unsigned j1, j2;
        TQ_ROUND(keys, j1, j2);
        if (lane == 2 * r)     sel = j1;
        if (lane == 2 * r + 1) sel = j2;
    }
    return sel;
}

// shared tile setup: load x[b] transposed into [512][20] with sq in column 16
__device__ __forceinline__ void load_tile(float* tile, const float4* x4, int tid)
{
    #pragma unroll
    for (int i = tid; i < NN * DDIM / 4; i += NT) {
        int row = i >> 2, part = i & 3;
        *(float4*)(tile + row * STRIDE + part * 4) = x4[i];
    }
    __syncthreads();
    #pragma unroll
    for (int r = tid; r < NN; r += NT) {
        const float* rp = tile + r * STRIDE;
        float s = rp[0] * rp[0];
        #pragma unroll
        for (int d = 1; d < DDIM; d++) s = fmaf(rp[d], rp[d], s);
        tile[r * STRIDE + 16] = s;     // same fma order as dist16 -> self strictly min
    }
}

// ---------------------------------------------------------------------------
// Stage 1: KNN on raw points + weighted Frechet mean fused into the rounds.
// (R9 form: fused + branchy advance — 28.4us measured.)
// ---------------------------------------------------------------------------
__global__ void __launch_bounds__(NT, 4) stage1_kernel(
    const float* __restrict__ x, const float* __restrict__ w_fm1)
{
    float* tile = (float*)smem_raw;                // [512][20]
    float* wc   = tile + NN * STRIDE;              // [20]

    const int tid = threadIdx.x, lane = tid & 31, warp = tid >> 5;
    const int b = blockIdx.y;

    load_tile(tile, (const float4*)(x + (size_t)b * NN * DDIM), tid);
    if (tid == 0) {
        float mx = -1e30f;
        for (int k = 0; k < KNN; k++) mx = fmaxf(mx, w_fm1[k]);
        float e[KNN], s = 0.f;
        for (int k = 0; k < KNN; k++) { e[k] = expf(w_fm1[k] - mx); s += e[k]; }
        float inv = 1.f / s;
        for (int k = 0; k < KNN; k++) wc[k] = e[k] * inv;
    }
    __syncthreads();

    const int n = blockIdx.x * WPB + warp;         // 1 query per warp
    ull keys[16];
    dist16(tile, n, lane, keys);
    sort16(keys);

    const int d = lane & 15;
    float acc = 0.f;
    #pragma unroll
    for (int r = 0; r < KNN / 2; r++) {
        unsigned j1, j2;
        TQ_ROUND(keys, j1, j2);
        acc = fmaf(wc[2 * r],     tile[j1 * STRIDE + d], acc);
        acc = fmaf(wc[2 * r + 1], tile[j2 * STRIDE + d], acc);
    }
    if (lane < DDIM)
        g_feat[((size_t)b * NN + n) * DDIM + lane] = acc;
}

// ---------------------------------------------------------------------------
// Stage 2: KNN on g (same ordering as KNN on the rank-1 lifted features);
// unfused topk (keys die before accumulators); epilogue in packed f32x2:
// fm2[d,f] = sum_k g[nn_k,d]*A[k,f],  A = sum_c softmax(w_fm2)[c,:]*w_mix1[c]*w_mix2[c,:]
// pooled[n] = mean_f sqrt(sum_d (fm2[d,f]-m_last[d,f])^2 + 1e-8)
// ---------------------------------------------------------------------------
__global__ void __launch_bounds__(NT, 4) stage2_kernel(
    const float* __restrict__ w_fm2, const float* __restrict__ w_mix1,
    const float* __restrict__ w_mix2, const float* __restrict__ m_last)
{
    float* tile = (float*)smem_raw;                        // [512][20] = 40960B
    ull*   Aa   = (ull*)(smem_raw + 40960);                // [20][32] dup(a0)   5120B
    ull*   Ab   = (ull*)(smem_raw + 40960 + 5120);         // [20][32] dup(a1)   5120B
    float* R    = (float*)(smem_raw + 40960 + 10240);      // wc2[30][20] then ms[16][50]

    const int tid = threadIdx.x, lane = tid & 31, warp = tid >> 5;
    const int b = blockIdx.y;

    load_tile(tile, (const float4*)(g_feat + (size_t)b * NN * DDIM), tid);
    // wc2 into R (per-channel softmax rows of w_fm2)
    if (tid < CC) {
        const float* row = w_fm2 + tid * KNN;
        float mx = -1e30f;
        for (int k = 0; k < KNN; k++) mx = fmaxf(mx, row[k]);
        float e[KNN], s = 0.f;
        for (int k = 0; k < KNN; k++) { e[k] = expf(row[k] - mx); s += e[k]; }
        float inv = 1.f / s;
        for (int k = 0; k < KNN; k++) R[tid * KNN + k] = e[k] * inv;
    }
    __syncthreads();   // sq (from load_tile) + wc2 visible

    // Aa[k][f] = dup(sum_c wc2[c][k]*w_mix1[c]*w_mix2[c][f]), Ab = dup(.. f+32)
    for (int i = tid; i < KNN * 32; i += NT) {
        int k = i >> 5, f = i & 31;
        float a0 = 0.f;
        #pragma unroll
        for (int c = 0; c < CC; c++)
            a0 = fmaf(R[c * KNN + k] * __ldg(w_mix1 + c), __ldg(w_mix2 + c * FF + f), a0);
        Aa[i] = dup2(a0);
        float a1 = 0.f;
        if (f + 32 < FF) {
            #pragma unroll
            for (int c = 0; c < CC; c++)
                a1 = fmaf(R[c * KNN + k] * __ldg(w_mix1 + c), __ldg(w_mix2 + c * FF + f + 32), a1);
        }
        Ab[i] = dup2(a1);
    }
    __syncthreads();   // Aa/Ab done; wc2 dead — reuse R for ms
    for (int i = tid; i < DDIM * FF; i += NT) R[i] = m_last[i];
    __syncthreads();

    const int n = blockIdx.x * WPB + warp;
    ull keys[16];
    dist16(tile, n, lane, keys);
    sort16(keys);
    unsigned sel = topk20(keys, lane);             // keys dead after this

    // packed epilogue: accA[i] accumulates fm2 for channel f0=lane, d=(2i,2i+1);
    // accB for channel f1=lane+32.
    ull accA[8], accB[8];
    #pragma unroll
    for (int i = 0; i < 8; i++) { accA[i] = 0ull; accB[i] = 0ull; }
    #pragma unroll
    for (int k = 0; k < KNN; k++) {
        unsigned idx = __shfl_sync(FULLM, sel, k);
        ull a0d = Aa[k * 32 + lane];               // (a0,a0)
        ull a1d = Ab[k * 32 + lane];               // (a1,a1) or (0,0)
        const ulonglong2* row = (const ulonglong2*)(tile + idx * STRIDE);
        ulonglong2 p0 = row[0], p1 = row[1];       // p0.x=(d0,d1) p0.y=(d2,d3) ...
        FMA2(accA[0], p0.x, a0d); FMA2(accB[0], p0.x, a1d);
        FMA2(accA[1], p0.y, a0d); FMA2(accB[1], p0.y, a1d);
        FMA2(accA[2], p1.x, a0d); FMA2(accB[2], p1.x, a1d);
        FMA2(accA[3], p1.y, a0d); FMA2(accB[3], p1.y, a1d);
        ulonglong2 p2 = row[2], p3 = row[3];
        FMA2(accA[4], p2.x, a0d); FMA2(accB[4], p2.x, a1d);
        FMA2(accA[5], p2.y, a0d); FMA2(accB[5], p2.y, a1d);
        FMA2(accA[6], p3.x, a0d); FMA2(accB[6], p3.x, a1d);
        FMA2(accA[7], p3.y, a0d); FMA2(accB[7], p3.y, a1d);
    }

    // unpack and finish (scalar tail; same per-element fma order as before)
    const int f0 = lane, f1 = lane + 32;
    const bool v1 = (f1 < FF);
    float acc0[DDIM], acc1[DDIM];
    #pragma unroll
    for (int i = 0; i < 8; i++) {
        acc0[2 * i]     = __uint_as_float((unsigned)accA[i]);
        acc0[2 * i + 1] = __uint_as_float((unsigned)(accA[i] >> 32));
        acc1[2 * i]     = __uint_as_float((unsigned)accB[i]);
        acc1[2 * i + 1] = __uint_as_float((unsigned)(accB[i] >> 32));
    }
    float s0 = 0.f, s1 = 0.f;
    #pragma unroll
    for (int dd = 0; dd < DDIM; dd++) {
        float d0 = acc0[dd] - R[dd * FF + f0];
        s0 = fmaf(d0, d0, s0);
        float d1 = acc1[dd] - (v1 ? R[dd * FF + f1] : 0.f);
        s1 = fmaf(d1, d1, s1);
    }
    float per = sqrtf(s0 + 1e-8f) + (v1 ? sqrtf(s1 + 1e-8f) : 0.f);
    #pragma unroll
    for (int off = 16; off; off >>= 1)
        per += __shfl_xor_sync(FULLM, per, off);
    if (lane == 0)
        g_pooled[(size_t)b * NN + n] = per * (1.f / (float)FF);
}

// ---------------------------------------------------------------------------
// Final classifier: out[b][j] = sum_n pooled[b][n]*w_cls[n][j] + b_cls[j]
// Parallelized: 40 classes x 12 n-chunks, smem tree reduce.
// ---------------------------------------------------------------------------
#define CLS_CH 12
__global__ void __launch_bounds__(512) cls_kernel(
    const float* __restrict__ w_cls, const float* __restrict__ b_cls,
    float* __restrict__ out)
{
    __shared__ float ps[NN];
    __shared__ float part[CLS_CH][NCLS];
    const int tid = threadIdx.x;
    const int b = blockIdx.x;
    ps[tid] = g_pooled[(size_t)b * NN + tid];
    __syncthreads();
    if (tid < NCLS * CLS_CH) {
        int j = tid % NCLS, c = tid / NCLS;
        int n0 = c * 43, n1 = min(NN, n0 + 43);
        float a = 0.f;
        for (int n = n0; n < n1; n++)
            a = fmaf(ps[n], w_cls[n * NCLS + j], a);
        part[c][j] = a;
    }
    __syncthreads();
    if (tid < NCLS) {
        float a = b_cls[tid];
        #pragma unroll
        for (int c = 0; c < CLS_CH; c++) a += part[c][tid];
        out[b * NCLS + tid] = a;
    }
}

extern "C" void kernel_launch(void* const* d_in, const int* in_sizes, int n_in,
                              void* d_out, int out_size)
{
    const float* x      = (const float*)d_in[0];  // [16,512,16,1]
    const float* w_fm1  = (const float*)d_in[1];  // [1,20]
    const float* w_mix1 = (const float*)d_in[2];  // [1,30]
    const float* w_fm2  = (const float*)d_in[3];  // [30,20]
    const float* w_mix2 = (const float*)d_in[4];  // [30,50]
    const float* m_last = (const float*)d_in[5];  // [16,50]
    const float* w_cls  = (const float*)d_in[6];  // [512,40]
    const float* b_cls  = (const float*)d_in[7];  // [40]
    float* out = (float*)d_out;                   // [16,40]

    constexpr size_t S1_SMEM = ((size_t)NN * STRIDE + KNN) * 4;          // 41040
    constexpr size_t S2_SMEM = 40960 + 10240 + 3200;                     // 54400

    cudaFuncSetAttribute(stage1_kernel, cudaFuncAttributeMaxDynamicSharedMemorySize, (int)S1_SMEM);
    cudaFuncSetAttribute(stage2_kernel, cudaFuncAttributeMaxDynamicSharedMemorySize, (int)S2_SMEM);

    dim3 grid(BPB, BB);   // 64 x 16 = 1024 blocks, 1 query per warp
    stage1_kernel<<<grid, NT, S1_SMEM>>>(x, w_fm1);
    stage2_kernel<<<grid, NT, S2_SMEM>>>(w_fm2, w_mix1, w_mix2, m_last);
    cls_kernel<<<BB, 512>>>(w_cls, b_cls, out);
}

// round 12
// speedup vs baseline: 1.4817x; 1.2044x over previous
#include <cuda_runtime.h>

#define BB    16
#define NN    512
#define DDIM  16
#define KNN   20
#define CC    30
#define FF    50
#define NCLS  40
#define NT    256      // threads per block (8 warps)
#define WPB   8
#define BPB   64       // blocks per batch (grid.x); 1 query per warp
#define STRIDE 20      // floats per tile row: 16 coords + sq at [16] (conflict-free)
#define FULLM 0xFFFFFFFFu

typedef unsigned long long ull;

// Scratch / precomputed tables (device globals — no allocation allowed)
__device__ float g_feat[BB * NN * DDIM];
__device__ float g_pooled[BB * NN];
__device__ float g_wc[KNN];          // softmax(w_fm1)
__device__ ull   g_Aa[KNN * 32];     // dup2(A[k][f]),    f = 0..31
__device__ ull   g_Ab[KNN * 32];     // dup2(A[k][f+32]), 0 beyond FF

extern __shared__ char smem_raw[];

__device__ __forceinline__ unsigned forder(float f) {
    unsigned u = __float_as_uint(f);
    return u ^ (((unsigned)((int)u >> 31)) | 0x80000000u);
}

__device__ __forceinline__ ull dup2(float v) {
    unsigned u = __float_as_uint(v);
    return ((ull)u << 32) | u;
}

// packed fp32x2 fma: acc = xv2*a2 + acc (two independent IEEE fp32 FMAs)
#define FMA2(acc, xv2, a2) \
    asm("fma.rn.f32x2 %0, %1, %2, %3;" : "=l"(acc) : "l"(xv2), "l"(a2), "l"(acc))

__device__ __forceinline__ float lo32(ull v) { return __uint_as_float((unsigned)v); }
__device__ __forceinline__ float hi32(ull v) { return __uint_as_float((unsigned)(v >> 32)); }

// in-register bitonic sort of 16 u64 keys, ascending
__device__ __forceinline__ void sort16(ull* keys) {
    #pragma unroll
    for (int k = 2; k <= 16; k <<= 1) {
        #pragma unroll
        for (int j = k >> 1; j > 0; j >>= 1) {
            #pragma unroll
            for (int i = 0; i < 16; i++) {
                int l = i ^ j;
                if (l > i) {
                    bool up = ((i & k) == 0);
                    ull a = keys[i], b = keys[l];
                    bool sw = up ? (a > b) : (a < b);
                    keys[i] = sw ? b : a;
                    keys[l] = sw ? a : b;
                }
            }
        }
    }
}

// distances (shifted by -sq[n]: same ordering) of this lane's 16 candidates
// j = lane+32i to query n -> packed (dist,idx) keys. Packed f32x2 dot:
// acc_lo = sum_{even d} q_d r_d, acc_hi = sum_{odd d}; dot = lo + hi.
__device__ __forceinline__ void dist16(
    const float* __restrict__ tile, int n, int lane, ull* keys)
{
    const ulonglong2* qp = (const ulonglong2*)(tile + n * STRIDE);
    ulonglong2 qa = qp[0], qb = qp[1];
    #pragma unroll
    for (int i = 0; i < 16; i++) {
        int j = lane + 32 * i;
        const float* rp = tile + j * STRIDE;
        const ulonglong2* rr = (const ulonglong2*)rp;
        ulonglong2 ra = rr[0], rb = rr[1];
        ull acc = 0ull;
        FMA2(acc, qa.x, ra.x); FMA2(acc, qa.y, ra.y);
        FMA2(acc, qb.x, rb.x); FMA2(acc, qb.y, rb.y);
        const ulonglong2* qp2 = (const ulonglong2*)(tile + n * STRIDE + 8);
        ulonglong2 qc = qp2[0], qd = qp2[1];
        const ulonglong2* rr2 = (const ulonglong2*)(rp + 8);
        ulonglong2 rc = rr2[0], rd = rr2[1];
        FMA2(acc, qc.x, rc.x); FMA2(acc, qc.y, rc.y);
        FMA2(acc, qd.x, rd.x); FMA2(acc, qd.y, rd.y);
        float dot  = lo32(acc) + hi32(acc);
        float dist = fmaf(-2.f, dot, rp[16]);   // sq[j] - 2*dot  (order-equivalent)
        keys[i] = ((ull)forder(dist) << 32) | (unsigned)j;
    }
}

// One double-pop tournament round (exact, unique keys; ties -> lowest index ==
// stable jax top_k). Emits winner indices J1, J2 (valid in ALL lanes).
// BRANCHY advance (measured faster than predicated shift in R10).
#define TQ_ROUND(keys, J1, J2)                                                  \
    {                                                                           \
        unsigned hi0 = (unsigned)((keys)[0] >> 32), lo0 = (unsigned)(keys)[0];  \
        unsigned hi1 = (unsigned)((keys)[1] >> 32), lo1 = (unsigned)(keys)[1];  \
        unsigned mhi1 = __reduce_min_sync(FULLM, hi0);                          \
        unsigned c1   = (hi0 == mhi1) ? lo0 : FULLM;                            \
        unsigned mlo1 = __reduce_min_sync(FULLM, c1);                           \
        bool win1 = (hi0 == mhi1) && (lo0 == mlo1);                             \
        unsigned chi = win1 ? hi1 : hi0, clo = win1 ? lo1 : lo0;                \
        unsigned mhi2 = __reduce_min_sync(FULLM, chi);                          \
        unsigned c2   = (chi == mhi2) ? clo : FULLM;                            \
        unsigned mlo2 = __reduce_min_sync(FULLM, c2);                           \
        bool win2 = (chi == mhi2) && (clo == mlo2);                             \
        (J1) = mlo1; (J2) = mlo2;                                               \
        int adv = (int)win1 + (int)win2;                                        \
        if (adv) {                                                              \
            _Pragma("unroll")                                                   \
            for (int _i = 0; _i < 15; _i++) (keys)[_i] = (keys)[_i + 1];        \
            (keys)[15] = ~0ull;                                                 \
            if (adv == 2) {                                                     \
                _Pragma("unroll")                                               \
                for (int _i = 0; _i < 15; _i++) (keys)[_i] = (keys)[_i + 1];    \
                (keys)[15] = ~0ull;                                             \
            }                                                                   \
        }                                                                       \
    }

// Exact ranked top-20 (unfused): lane r (r<20) ends holding the index of the
// r-th nearest neighbor. keys fully consumed (dead afterwards).
__device__ __forceinline__ unsigned topk20(ull* keys, int lane)
{
    unsigned sel = 0;
    #pragma unroll
    for (int r = 0; r < KNN / 2; r++) {
        unsigned j1, j2;
        TQ_ROUND(keys, j1, j2);
        if (lane == 2 * r)     sel = j1;
        if (lane == 2 * r + 1) sel = j2;
    }
    return sel;
}

// shared tile setup: load x[b] transposed into [512][20] with sq in column 16.
// sq uses the SAME f32x2 even/odd tree as dist16 -> self-dist = -sq exactly.
__device__ __forceinline__ void load_tile(float* tile, const float4* x4, int tid)
{
    #pragma unroll
    for (int i = tid; i < NN * DDIM / 4; i += NT) {
        int row = i >> 2, part = i & 3;
        *(float4*)(tile + row * STRIDE + part * 4) = x4[i];
    }
    __syncthreads();
    #pragma unroll
    for (int r = tid; r < NN; r += NT) {
        const ulonglong2* rp = (const ulonglong2*)(tile + r * STRIDE);
        ulonglong2 a = rp[0], b = rp[1], c = rp[2], d = rp[3];
        ull acc = 0ull;
        FMA2(acc, a.x, a.x); FMA2(acc, a.y, a.y);
        FMA2(acc, b.x, b.x); FMA2(acc, b.y, b.y);
        FMA2(acc, c.x, c.x); FMA2(acc, c.y, c.y);
        FMA2(acc, d.x, d.x); FMA2(acc, d.y, d.y);
        tile[r * STRIDE + 16] = lo32(acc) + hi32(acc);
    }
}

// ---------------------------------------------------------------------------
// Prep: weight-only tables, computed ONCE (removes per-block redundancy).
// ---------------------------------------------------------------------------
__global__ void prep_kernel(
    const float* __restrict__ w_fm1, const float* __restrict__ w_fm2,
    const float* __restrict__ w_mix1, const float* __restrict__ w_mix2)
{
    __shared__ float wc2[CC * KNN];
    const int tid = threadIdx.x;
    if (tid == 0) {
        float mx = -1e30f;
        for (int k = 0; k < KNN; k++) mx = fmaxf(mx, w_fm1[k]);
        float e[KNN], s = 0.f;
        for (int k = 0; k < KNN; k++) { e[k] = expf(w_fm1[k] - mx); s += e[k]; }
        float inv = 1.f / s;
        for (int k = 0; k < KNN; k++) g_wc[k] = e[k] * inv;
    }
    if (tid < CC) {
        const float* row = w_fm2 + tid * KNN;
        float mx = -1e30f;
        for (int k = 0; k < KNN; k++) mx = fmaxf(mx, row[k]);
        float e[KNN], s = 0.f;
        for (int k = 0; k < KNN; k++) { e[k] = expf(row[k] - mx); s += e[k]; }
        float inv = 1.f / s;
        for (int k = 0; k < KNN; k++) wc2[tid * KNN + k] = e[k] * inv;
    }
    __syncthreads();
    for (int i = tid; i < KNN * 32; i += NT) {
        int k = i >> 5, f = i & 31;
        float a0 = 0.f;
        #pragma unroll
        for (int c = 0; c < CC; c++)
            a0 = fmaf(wc2[c * KNN + k] * w_mix1[c], w_mix2[c * FF + f], a0);
        g_Aa[i] = dup2(a0);
        float a1 = 0.f;
        if (f + 32 < FF) {
            #pragma unroll
            for (int c = 0; c < CC; c++)
                a1 = fmaf(wc2[c * KNN + k] * w_mix1[c], w_mix2[c * FF + f + 32], a1);
        }
        g_Ab[i] = dup2(a1);
    }
}

// ---------------------------------------------------------------------------
// Stage 1: KNN on raw points + weighted Frechet mean fused into the rounds.
// ---------------------------------------------------------------------------
__global__ void __launch_bounds__(NT, 4) stage1_kernel(const float* __restrict__ x)
{
    float* tile = (float*)smem_raw;                // [512][20]
    float* wc   = tile + NN * STRIDE;              // [20]

    const int tid = threadIdx.x, lane = tid & 31, warp = tid >> 5;
    const int b = blockIdx.y;

    load_tile(tile, (const float4*)(x + (size_t)b * NN * DDIM), tid);
    if (tid < KNN) wc[tid] = g_wc[tid];
    __syncthreads();

    const int n = blockIdx.x * WPB + warp;         // 1 query per warp
    ull keys[16];
    dist16(tile, n, lane, keys);
    sort16(keys);

    const int d = lane & 15;
    float acc = 0.f;
    #pragma unroll
    for (int r = 0; r < KNN / 2; r++) {
        unsigned j1, j2;
        TQ_ROUND(keys, j1, j2);
        acc = fmaf(wc[2 * r],     tile[j1 * STRIDE + d], acc);
        acc = fmaf(wc[2 * r + 1], tile[j2 * STRIDE + d], acc);
    }
    if (lane < DDIM)
        g_feat[((size_t)b * NN + n) * DDIM + lane] = acc;
}

// ---------------------------------------------------------------------------
// Stage 2: KNN on g (same ordering as KNN on the rank-1 lifted features);
// unfused topk (keys die before accumulators); epilogue in packed f32x2:
// fm2[d,f] = sum_k g[nn_k,d]*A[k,f]; pooled = mean_f ||fm2[:,f]-m_last[:,f]||.
// ---------------------------------------------------------------------------
__global__ void __launch_bounds__(NT, 4) stage2_kernel(
    const float* __restrict__ m_last)
{
    float* tile = (float*)smem_raw;                        // [512][20] = 40960B
    ull*   Aa   = (ull*)(smem_raw + 40960);                // [20][32] dup(a0)   5120B
    ull*   Ab   = (ull*)(smem_raw + 40960 + 5120);         // [20][32] dup(a1)   5120B
    float* ms   = (float*)(smem_raw + 40960 + 10240);      // [16][50]           3200B

    const int tid = threadIdx.x, lane = tid & 31, warp = tid >> 5;
    const int b = blockIdx.y;

    load_tile(tile, (const float4*)(g_feat + (size_t)b * NN * DDIM), tid);
    #pragma unroll
    for (int i = tid; i < KNN * 32; i += NT) { Aa[i] = g_Aa[i]; Ab[i] = g_Ab[i]; }
    for (int i = tid; i < DDIM * FF; i += NT) ms[i] = m_last[i];
    __syncthreads();

    const int n = blockIdx.x * WPB + warp;
    ull keys[16];
    dist16(tile, n, lane, keys);
    sort16(keys);
    unsigned sel = topk20(keys, lane);             // keys dead after this

    ull accA[8], accB[8];
    #pragma unroll
    for (int i = 0; i < 8; i++) { accA[i] = 0ull; accB[i] = 0ull; }
    #pragma unroll
    for (int k = 0; k < KNN; k++) {
        unsigned idx = __shfl_sync(FULLM, sel, k);
        ull a0d = Aa[k * 32 + lane];               // (a0,a0)
        ull a1d = Ab[k * 32 + lane];               // (a1,a1) or (0,0)
        const ulonglong2* row = (const ulonglong2*)(tile + idx * STRIDE);
        ulonglong2 p0 = row[0], p1 = row[1];
        FMA2(accA[0], p0.x, a0d); FMA2(accB[0], p0.x, a1d);
        FMA2(accA[1], p0.y, a0d); FMA2(accB[1], p0.y, a1d);
        FMA2(accA[2], p1.x, a0d); FMA2(accB[2], p1.x, a1d);
        FMA2(accA[3], p1.y, a0d); FMA2(accB[3], p1.y, a1d);
        ulonglong2 p2 = row[2], p3 = row[3];
        FMA2(accA[4], p2.x, a0d); FMA2(accB[4], p2.x, a1d);
        FMA2(accA[5], p2.y, a0d); FMA2(accB[5], p2.y, a1d);
        FMA2(accA[6], p3.x, a0d); FMA2(accB[6], p3.x, a1d);
        FMA2(accA[7], p3.y, a0d); FMA2(accB[7], p3.y, a1d);
    }

    const int f0 = lane, f1 = lane + 32;
    const bool v1 = (f1 < FF);
    float s0 = 0.f, s1 = 0.f;
    #pragma unroll
    for (int i = 0; i < 8; i++) {
        float e0 = lo32(accA[i]) - ms[(2 * i)     * FF + f0];
        float e1 = hi32(accA[i]) - ms[(2 * i + 1) * FF + f0];
        s0 = fmaf(e0, e0, s0); s0 = fmaf(e1, e1, s0);
        float e2 = lo32(accB[i]) - (v1 ? ms[(2 * i)     * FF + f1] : 0.f);
        float e3 = hi32(accB[i]) - (v1 ? ms[(2 * i + 1) * FF + f1] : 0.f);
        s1 = fmaf(e2, e2, s1); s1 = fmaf(e3, e3, s1);
    }
    float per = sqrtf(s0 + 1e-8f) + (v1 ? sqrtf(s1 + 1e-8f) : 0.f);
    #pragma unroll
    for (int off = 16; off; off >>= 1)
        per += __shfl_xor_sync(FULLM, per, off);
    if (lane == 0)
        g_pooled[(size_t)b * NN + n] = per * (1.f / (float)FF);
}

// ---------------------------------------------------------------------------
// Final classifier: out[b][j] = sum_n pooled[b][n]*w_cls[n][j] + b_cls[j]
// ---------------------------------------------------------------------------
#define CLS_CH 12
__global__ void __launch_bounds__(512) cls_kernel(
    const float* __restrict__ w_cls, const float* __restrict__ b_cls,
    float* __restrict__ out)
{
    __shared__ float ps[NN];
    __shared__ float part[CLS_CH][NCLS];
    const int tid = threadIdx.x;
    const int b = blockIdx.x;
    ps[tid] = g_pooled[(size_t)b * NN + tid];
    __syncthreads();
    if (tid < NCLS * CLS_CH) {
        int j = tid % NCLS, c = tid / NCLS;
        int n0 = c * 43, n1 = min(NN, n0 + 43);
        float a = 0.f;
        for (int n = n0; n < n1; n++)
            a = fmaf(ps[n], w_cls[n * NCLS + j], a);
        part[c][j] = a;
    }
    __syncthreads();
    if (tid < NCLS) {
        float a = b_cls[tid];
        #pragma unroll
        for (int c = 0; c < CLS_CH; c++) a += part[c][tid];
        out[b * NCLS + tid] = a;
    }
}

extern "C" void kernel_launch(void* const* d_in, const int* in_sizes, int n_in,
                              void* d_out, int out_size)
{
    const float* x      = (const float*)d_in[0];  // [16,512,16,1]
    const float* w_fm1  = (const float*)d_in[1];  // [1,20]
    const float* w_mix1 = (const float*)d_in[2];  // [1,30]
    const float* w_fm2  = (const float*)d_in[3];  // [30,20]
    const float* w_mix2 = (const float*)d_in[4];  // [30,50]
    const float* m_last = (const float*)d_in[5];  // [16,50]
    const float* w_cls  = (const float*)d_in[6];  // [512,40]
    const float* b_cls  = (const float*)d_in[7];  // [40]
    float* out = (float*)d_out;                   // [16,40]

    constexpr size_t S1_SMEM = ((size_t)NN * STRIDE + KNN) * 4;          // 41040
    constexpr size_t S2_SMEM = 40960 + 10240 + 3200;                     // 54400

    cudaFuncSetAttribute(stage1_kernel, cudaFuncAttributeMaxDynamicSharedMemorySize, (int)S1_SMEM);
    cudaFuncSetAttribute(stage2_kernel, cudaFuncAttributeMaxDynamicSharedMemorySize, (int)S2_SMEM);

    dim3 grid(BPB, BB);   // 64 x 16 = 1024 blocks, 1 query per warp
    prep_kernel<<<1, NT>>>(w_fm1, w_fm2, w_mix1, w_mix2);
    stage1_kernel<<<grid, NT, S1_SMEM>>>(x);
    stage2_kernel<<<grid, NT, S2_SMEM>>>(m_last);
    cls_kernel<<<BB, 512>>>(w_cls, b_cls, out);
}

// round 13
// speedup vs baseline: 1.5284x; 1.0315x over previous
#include <cuda_runtime.h>

#define BB    16
#define NN    512
#define DDIM  16
#define KNN   20
#define CC    30
#define FF    50
#define NCLS  40
#define NT    256      // threads per block (8 warps)
#define WPB   8
#define BPB   64       // blocks per batch (grid.x); 1 query per warp
#define STRIDE 20      // floats per tile row: 16 coords + sq at [16] (conflict-free)
#define FULLM 0xFFFFFFFFu

typedef unsigned long long ull;

// Scratch / precomputed tables (device globals — no allocation allowed)
__device__ float g_feat[BB * NN * DDIM];
__device__ float g_pooled[BB * NN];
__device__ ull   g_Aa[KNN * 32];     // dup2(A[k][f]),    f = 0..31
__device__ ull   g_Ab[KNN * 32];     // dup2(A[k][f+32]), 0 beyond FF

extern __shared__ char smem_raw[];

__device__ __forceinline__ unsigned forder(float f) {
    unsigned u = __float_as_uint(f);
    return u ^ (((unsigned)((int)u >> 31)) | 0x80000000u);
}

__device__ __forceinline__ ull dup2(float v) {
    unsigned u = __float_as_uint(v);
    return ((ull)u << 32) | u;
}

// packed fp32x2 fma: acc = xv2*a2 + acc (two independent IEEE fp32 FMAs)
#define FMA2(acc, xv2, a2) \
    asm("fma.rn.f32x2 %0, %1, %2, %3;" : "=l"(acc) : "l"(xv2), "l"(a2), "l"(acc))

__device__ __forceinline__ float lo32(ull v) { return __uint_as_float((unsigned)v); }
__device__ __forceinline__ float hi32(ull v) { return __uint_as_float((unsigned)(v >> 32)); }

// in-register bitonic sort of 16 u64 keys, ascending
__device__ __forceinline__ void sort16(ull* keys) {
    #pragma unroll
    for (int k = 2; k <= 16; k <<= 1) {
        #pragma unroll
        for (int j = k >> 1; j > 0; j >>= 1) {
            #pragma unroll
            for (int i = 0; i < 16; i++) {
                int l = i ^ j;
                if (l > i) {
                    bool up = ((i & k) == 0);
                    ull a = keys[i], b = keys[l];
                    bool sw = up ? (a > b) : (a < b);
                    keys[i] = sw ? b : a;
                    keys[l] = sw ? a : b;
                }
            }
        }
    }
}

// distances (shifted by -sq[n]: same ordering) of this lane's 16 candidates
// j = lane+32i to query n -> packed (dist,idx) keys. Packed f32x2 dot.
__device__ __forceinline__ void dist16(
    const float* __restrict__ tile, int n, int lane, ull* keys)
{
    const ulonglong2* qp = (const ulonglong2*)(tile + n * STRIDE);
    ulonglong2 qa = qp[0], qb = qp[1];
    const ulonglong2* qp2 = (const ulonglong2*)(tile + n * STRIDE + 8);
    ulonglong2 qc = qp2[0], qd = qp2[1];
    #pragma unroll
    for (int i = 0; i < 16; i++) {
        int j = lane + 32 * i;
        const float* rp = tile + j * STRIDE;
        const ulonglong2* rr = (const ulonglong2*)rp;
        ulonglong2 ra = rr[0], rb = rr[1];
        ull acc = 0ull;
        FMA2(acc, qa.x, ra.x); FMA2(acc, qa.y, ra.y);
        FMA2(acc, qb.x, rb.x); FMA2(acc, qb.y, rb.y);
        const ulonglong2* rr2 = (const ulonglong2*)(rp + 8);
        ulonglong2 rc = rr2[0], rd = rr2[1];
        FMA2(acc, qc.x, rc.x); FMA2(acc, qc.y, rc.y);
        FMA2(acc, qd.x, rd.x); FMA2(acc, qd.y, rd.y);
        float dot  = lo32(acc) + hi32(acc);
        float dist = fmaf(-2.f, dot, rp[16]);   // sq[j] - 2*dot  (order-equivalent)
        keys[i] = ((ull)forder(dist) << 32) | (unsigned)j;
    }
}

// One double-pop tournament round (exact, unique keys; ties -> lowest index ==
// stable jax top_k). Emits winner indices J1, J2 (valid in ALL lanes).
#define TQ_ROUND(keys, J1, J2)                                                  \
    {                                                                           \
        unsigned hi0 = (unsigned)((keys)[0] >> 32), lo0 = (unsigned)(keys)[0];  \
        unsigned hi1 = (unsigned)((keys)[1] >> 32), lo1 = (unsigned)(keys)[1];  \
        unsigned mhi1 = __reduce_min_sync(FULLM, hi0);                          \
        unsigned c1   = (hi0 == mhi1) ? lo0 : FULLM;                            \
        unsigned mlo1 = __reduce_min_sync(FULLM, c1);                           \
        bool win1 = (hi0 == mhi1) && (lo0 == mlo1);                             \
        unsigned chi = win1 ? hi1 : hi0, clo = win1 ? lo1 : lo0;                \
        unsigned mhi2 = __reduce_min_sync(FULLM, chi);                          \
        unsigned c2   = (chi == mhi2) ? clo : FULLM;                            \
        unsigned mlo2 = __reduce_min_sync(FULLM, c2);                           \
        bool win2 = (chi == mhi2) && (clo == mlo2);                             \
        (J1) = mlo1; (J2) = mlo2;                                               \
        int adv = (int)win1 + (int)win2;                                        \
        if (adv) {                                                              \
            _Pragma("unroll")                                                   \
            for (int _i = 0; _i < 15; _i++) (keys)[_i] = (keys)[_i + 1];        \
            (keys)[15] = ~0ull;                                                 \
            if (adv == 2) {                                                     \
                _Pragma("unroll")                                               \
                for (int _i = 0; _i < 15; _i++) (keys)[_i] = (keys)[_i + 1];    \
                (keys)[15] = ~0ull;                                             \
            }                                                                   \
        }                                                                       \
    }

// Exact ranked top-20 (unfused): lane r (r<20) ends holding the index of the
// r-th nearest neighbor.
__device__ __forceinline__ unsigned topk20(ull* keys, int lane)
{
    unsigned sel = 0;
    #pragma unroll
    for (int r = 0; r < KNN / 2; r++) {
        unsigned j1, j2;
        TQ_ROUND(keys, j1, j2);
        if (lane == 2 * r)     sel = j1;
        if (lane == 2 * r + 1) sel = j2;
    }
    return sel;
}

// shared tile setup: load x[b] transposed into [512][20] with sq in column 16.
// sq uses the SAME f32x2 even/odd tree as dist16 -> self-dist = -sq exactly.
__device__ __forceinline__ void load_tile(float* tile, const float4* x4, int tid)
{
    #pragma unroll
    for (int i = tid; i < NN * DDIM / 4; i += NT) {
        int row = i >> 2, part = i & 3;
        *(float4*)(tile + row * STRIDE + part * 4) = x4[i];
    }
    __syncthreads();
    #pragma unroll
    for (int r = tid; r < NN; r += NT) {
        const ulonglong2* rp = (const ulonglong2*)(tile + r * STRIDE);
        ulonglong2 a = rp[0], b = rp[1], c = rp[2], d = rp[3];
        ull acc = 0ull;
        FMA2(acc, a.x, a.x); FMA2(acc, a.y, a.y);
        FMA2(acc, b.x, b.x); FMA2(acc, b.y, b.y);
        FMA2(acc, c.x, c.x); FMA2(acc, c.y, c.y);
        FMA2(acc, d.x, d.x); FMA2(acc, d.y, d.y);
        tile[r * STRIDE + 16] = lo32(acc) + hi32(acc);
    }
}

// ---------------------------------------------------------------------------
// Stage 1: KNN on raw points + weighted Frechet mean fused into the rounds.
// Block (0,0) additionally builds the stage-2 A tables (visible to stage2 via
// the kernel-boundary sync). No separate prep launch.
// ---------------------------------------------------------------------------
__global__ void __launch_bounds__(NT, 4) stage1_kernel(
    const float* __restrict__ x, const float* __restrict__ w_fm1,
    const float* __restrict__ w_fm2, const float* __restrict__ w_mix1,
    const float* __restrict__ w_mix2)
{
    float* tile = (float*)smem_raw;                // [512][20]  40960B
    float* wc   = tile + NN * STRIDE;              // [20]          80B
    float* wc2  = wc + KNN;                        // [30][20]    2400B (block 0,0 only)

    const int tid = threadIdx.x, lane = tid & 31, warp = tid >> 5;
    const int b = blockIdx.y;

    load_tile(tile, (const float4*)(x + (size_t)b * NN * DDIM), tid);
    if (tid == 0) {
        float mx = -1e30f;
        for (int k = 0; k < KNN; k++) mx = fmaxf(mx, w_fm1[k]);
        float e[KNN], s = 0.f;
        for (int k = 0; k < KNN; k++) { e[k] = expf(w_fm1[k] - mx); s += e[k]; }
        float inv = 1.f / s;
        for (int k = 0; k < KNN; k++) wc[k] = e[k] * inv;
    }

    // one block builds the stage-2 tables (uniform branch; block-local syncs ok)
    if (blockIdx.x == 0 && blockIdx.y == 0) {
        if (tid < CC) {
            const float* row = w_fm2 + tid * KNN;
            float mx = -1e30f;
            for (int k = 0; k < KNN; k++) mx = fmaxf(mx, row[k]);
            float e[KNN], s = 0.f;
            for (int k = 0; k < KNN; k++) { e[k] = expf(row[k] - mx); s += e[k]; }
            float inv = 1.f / s;
            for (int k = 0; k < KNN; k++) wc2[tid * KNN + k] = e[k] * inv;
        }
        __syncthreads();
        for (int i = tid; i < KNN * 32; i += NT) {
            int k = i >> 5, f = i & 31;
            float a0 = 0.f;
            #pragma unroll
            for (int c = 0; c < CC; c++)
                a0 = fmaf(wc2[c * KNN + k] * __ldg(w_mix1 + c), __ldg(w_mix2 + c * FF + f), a0);
            g_Aa[i] = dup2(a0);
            float a1 = 0.f;
            if (f + 32 < FF) {
                #pragma unroll
                for (int c = 0; c < CC; c++)
                    a1 = fmaf(wc2[c * KNN + k] * __ldg(w_mix1 + c), __ldg(w_mix2 + c * FF + f + 32), a1);
            }
            g_Ab[i] = dup2(a1);
        }
    }
    __syncthreads();

    const int n = blockIdx.x * WPB + warp;         // 1 query per warp
    ull keys[16];
    dist16(tile, n, lane, keys);
    sort16(keys);

    const int d = lane & 15;
    float acc = 0.f;
    #pragma unroll
    for (int r = 0; r < KNN / 2; r++) {
        unsigned j1, j2;
        TQ_ROUND(keys, j1, j2);
        acc = fmaf(wc[2 * r],     tile[j1 * STRIDE + d], acc);
        acc = fmaf(wc[2 * r + 1], tile[j2 * STRIDE + d], acc);
    }
    if (lane < DDIM)
        g_feat[((size_t)b * NN + n) * DDIM + lane] = acc;
}

// ---------------------------------------------------------------------------
// Stage 2: KNN on g; unfused topk; packed-f32x2 epilogue:
// fm2[d,f] = sum_k g[nn_k,d]*A[k,f]; pooled = mean_f ||fm2[:,f]-m_last[:,f]||.
// ---------------------------------------------------------------------------
__global__ void __launch_bounds__(NT, 4) stage2_kernel(
    const float* __restrict__ m_last)
{
    float* tile = (float*)smem_raw;                        // [512][20] = 40960B
    ull*   Aa   = (ull*)(smem_raw + 40960);                // [20][32] dup(a0)   5120B
    ull*   Ab   = (ull*)(smem_raw + 40960 + 5120);         // [20][32] dup(a1)   5120B
    float* ms   = (float*)(smem_raw + 40960 + 10240);      // [16][50]           3200B

    const int tid = threadIdx.x, lane = tid & 31, warp = tid >> 5;
    const int b = blockIdx.y;

    load_tile(tile, (const float4*)(g_feat + (size_t)b * NN * DDIM), tid);
    #pragma unroll
    for (int i = tid; i < KNN * 32; i += NT) { Aa[i] = g_Aa[i]; Ab[i] = g_Ab[i]; }
    for (int i = tid; i < DDIM * FF; i += NT) ms[i] = m_last[i];
    __syncthreads();

    const int n = blockIdx.x * WPB + warp;
    ull keys[16];
    dist16(tile, n, lane, keys);
    sort16(keys);
    unsigned sel = topk20(keys, lane);             // keys dead after this

    ull accA[8], accB[8];
    #pragma unroll
    for (int i = 0; i < 8; i++) { accA[i] = 0ull; accB[i] = 0ull; }
    #pragma unroll
    for (int k = 0; k < KNN; k++) {
        unsigned idx = __shfl_sync(FULLM, sel, k);
        ull a0d = Aa[k * 32 + lane];               // (a0,a0)
        ull a1d = Ab[k * 32 + lane];               // (a1,a1) or (0,0)
        const ulonglong2* row = (const ulonglong2*)(tile + idx * STRIDE);
        ulonglong2 p0 = row[0], p1 = row[1];
        FMA2(accA[0], p0.x, a0d); FMA2(accB[0], p0.x, a1d);
        FMA2(accA[1], p0.y, a0d); FMA2(accB[1], p0.y, a1d);
        FMA2(accA[2], p1.x, a0d); FMA2(accB[2], p1.x, a1d);
        FMA2(accA[3], p1.y, a0d); FMA2(accB[3], p1.y, a1d);
        ulonglong2 p2 = row[2], p3 = row[3];
        FMA2(accA[4], p2.x, a0d); FMA2(accB[4], p2.x, a1d);
        FMA2(accA[5], p2.y, a0d); FMA2(accB[5], p2.y, a1d);
        FMA2(accA[6], p3.x, a0d); FMA2(accB[6], p3.x, a1d);
        FMA2(accA[7], p3.y, a0d); FMA2(accB[7], p3.y, a1d);
    }

    const int f0 = lane, f1 = lane + 32;
    const bool v1 = (f1 < FF);
    float s0 = 0.f, s1 = 0.f;
    #pragma unroll
    for (int i = 0; i < 8; i++) {
        float e0 = lo32(accA[i]) - ms[(2 * i)     * FF + f0];
        float e1 = hi32(accA[i]) - ms[(2 * i + 1) * FF + f0];
        s0 = fmaf(e0, e0, s0); s0 = fmaf(e1, e1, s0);
        float e2 = lo32(accB[i]) - (v1 ? ms[(2 * i)     * FF + f1] : 0.f);
        float e3 = hi32(accB[i]) - (v1 ? ms[(2 * i + 1) * FF + f1] : 0.f);
        s1 = fmaf(e2, e2, s1); s1 = fmaf(e3, e3, s1);
    }
    float per = sqrtf(s0 + 1e-8f) + (v1 ? sqrtf(s1 + 1e-8f) : 0.f);
    #pragma unroll
    for (int off = 16; off; off >>= 1)
        per += __shfl_xor_sync(FULLM, per, off);
    if (lane == 0)
        g_pooled[(size_t)b * NN + n] = per * (1.f / (float)FF);
}

// ---------------------------------------------------------------------------
// Final classifier: out[b][j] = sum_n pooled[b][n]*w_cls[n][j] + b_cls[j].
// One block per (b, j): one product per thread + tree reduce (latency ~1 LDG).
// ---------------------------------------------------------------------------
__global__ void __launch_bounds__(NN) cls_kernel(
    const float* __restrict__ w_cls, const float* __restrict__ b_cls,
    float* __restrict__ out)
{
    __shared__ float ws[16];
    const int tid = threadIdx.x, lane = tid & 31, warp = tid >> 5;
    const int b = blockIdx.x, j = blockIdx.y;

    float v = g_pooled[(size_t)b * NN + tid] * __ldg(w_cls + (size_t)tid * NCLS + j);
    #pragma unroll
    for (int off = 16; off; off >>= 1)
        v += __shfl_xor_sync(FULLM, v, off);
    if (lane == 0) ws[warp] = v;
    __syncthreads();
    if (tid < 16) {
        float s = ws[tid];
        #pragma unroll
        for (int off = 8; off; off >>= 1)
            s += __shfl_xor_sync(0xFFFFu, s, off);
        if (tid == 0) out[b * NCLS + j] = s + __ldg(b_cls + j);
    }
}

extern "C" void kernel_launch(void* const* d_in, const int* in_sizes, int n_in,
                              void* d_out, int out_size)
{
    const float* x      = (const float*)d_in[0];  // [16,512,16,1]
    const float* w_fm1  = (const float*)d_in[1];  // [1,20]
    const float* w_mix1 = (const float*)d_in[2];  // [1,30]
    const float* w_fm2  = (const float*)d_in[3];  // [30,20]
    const float* w_mix2 = (const float*)d_in[4];  // [30,50]
    const float* m_last = (const float*)d_in[5];  // [16,50]
    const float* w_cls  = (const float*)d_in[6];  // [512,40]
    const float* b_cls  = (const float*)d_in[7];  // [40]
    float* out = (float*)d_out;                   // [16,40]

    constexpr size_t S1_SMEM = ((size_t)NN * STRIDE + KNN + CC * KNN) * 4;  // 43440
    constexpr size_t S2_SMEM = 40960 + 10240 + 3200;                        // 54400

    cudaFuncSetAttribute(stage1_kernel, cudaFuncAttributeMaxDynamicSharedMemorySize, (int)S1_SMEM);
    cudaFuncSetAttribute(stage2_kernel, cudaFuncAttributeMaxDynamicSharedMemorySize, (int)S2_SMEM);

    dim3 grid(BPB, BB);   // 64 x 16 = 1024 blocks, 1 query per warp
    stage1_kernel<<<grid, NT, S1_SMEM>>>(x, w_fm1, w_fm2, w_mix1, w_mix2);
    stage2_kernel<<<grid, NT, S2_SMEM>>>(m_last);
    cls_kernel<<<dim3(BB, NCLS), NN>>>(w_cls, b_cls, out);
}